// round 5
// baseline (speedup 1.0000x reference)
#include <cuda_runtime.h>
#include <math.h>
#include <stdint.h>

#define BATCH 2
#define SEQ   2048
#define DIM   2048
#define NH    16
#define NKVH  8
#define HDIM  128
#define NREP  2
#define QKV_O ((NH + 2 * NKVH) * HDIM)   // 4096
#define NTOK  (BATCH * SEQ)              // 4096

// ---------------- scratch (no allocations allowed) ----------------
__device__ float g_qkv[(size_t)NTOK * QKV_O];          // 64 MB
__device__ float g_q[(size_t)BATCH * NH * SEQ * HDIM]; // 32 MB
__device__ float g_k[(size_t)BATCH * NKVH * SEQ * HDIM];
__device__ float g_v[(size_t)BATCH * NKVH * SEQ * HDIM];
__device__ float g_ao[(size_t)NTOK * NH * HDIM];       // 32 MB

// =================================================================
// tf32 tensor-core NT GEMM: C[m,n] = sum_k A[m*K+k] * B[n*K+k]
// 128x128 block tile, BK=32, 256 threads (8 warps as 2x4),
// warp tile 64x32 = 4x4 mma.m16n8k8 tiles, fp32 accumulate.
// =================================================================
#define TBK 32
#define TST 36   // SMEM row stride (floats): conflict-free fragment LDS

__device__ __forceinline__ uint32_t f2tf32(float x) {
    uint32_t u;
    asm("cvt.rna.tf32.f32 %0, %1;" : "=r"(u) : "f"(x));
    return u;
}

__global__ __launch_bounds__(256) void gemm_nt_tf32(
    const float* __restrict__ A, const float* __restrict__ Bm,
    float* __restrict__ C, int M, int N, int K)
{
    __shared__ float As[128 * TST];
    __shared__ float Bs[128 * TST];

    const int t    = threadIdx.x;
    const int lane = t & 31;
    const int wid  = t >> 5;
    const int g    = lane >> 2;     // groupID 0..7
    const int tig  = lane & 3;      // thread-in-group 0..3
    const int wm   = (wid >> 2) * 64;   // warp M offset in tile
    const int wn   = (wid & 3) * 32;    // warp N offset in tile

    const int m0 = blockIdx.y * 128;
    const int n0 = blockIdx.x * 128;

    const int lrow = t >> 1;            // 0..127
    const int lkb  = (t & 1) * 16;      // 0 or 16

    const float* Ag = A  + (size_t)(m0 + lrow) * K + lkb;
    const float* Bg = Bm + (size_t)(n0 + lrow) * K + lkb;

    float acc[4][4][4];
#pragma unroll
    for (int i = 0; i < 4; i++)
#pragma unroll
        for (int j = 0; j < 4; j++)
#pragma unroll
            for (int c = 0; c < 4; c++) acc[i][j][c] = 0.f;

    for (int k0 = 0; k0 < K; k0 += TBK) {
        // ---- load 128x32 A and B tiles, round to tf32, store k-major ----
#pragma unroll
        for (int i = 0; i < 4; i++) {
            float4 a = *(const float4*)(Ag + k0 + i * 4);
            float4 b = *(const float4*)(Bg + k0 + i * 4);
            float4 at, bt;
            at.x = __uint_as_float(f2tf32(a.x)); at.y = __uint_as_float(f2tf32(a.y));
            at.z = __uint_as_float(f2tf32(a.z)); at.w = __uint_as_float(f2tf32(a.w));
            bt.x = __uint_as_float(f2tf32(b.x)); bt.y = __uint_as_float(f2tf32(b.y));
            bt.z = __uint_as_float(f2tf32(b.z)); bt.w = __uint_as_float(f2tf32(b.w));
            *(float4*)&As[lrow * TST + lkb + i * 4] = at;
            *(float4*)&Bs[lrow * TST + lkb + i * 4] = bt;
        }
        __syncthreads();

        // ---- 4 k-chunks of 8 ----
#pragma unroll
        for (int kc = 0; kc < 4; kc++) {
            uint32_t af[4][4];
            uint32_t bf[4][2];
#pragma unroll
            for (int mt = 0; mt < 4; mt++) {
                const float* p = &As[(wm + mt * 16 + g) * TST + kc * 8 + tig];
                af[mt][0] = __float_as_uint(p[0]);
                af[mt][1] = __float_as_uint(p[8 * TST]);
                af[mt][2] = __float_as_uint(p[4]);
                af[mt][3] = __float_as_uint(p[8 * TST + 4]);
            }
#pragma unroll
            for (int nt = 0; nt < 4; nt++) {
                const float* p = &Bs[(wn + nt * 8 + g) * TST + kc * 8 + tig];
                bf[nt][0] = __float_as_uint(p[0]);
                bf[nt][1] = __float_as_uint(p[4]);
            }
#pragma unroll
            for (int mt = 0; mt < 4; mt++)
#pragma unroll
                for (int nt = 0; nt < 4; nt++) {
                    asm volatile(
                        "mma.sync.aligned.m16n8k8.row.col.f32.tf32.tf32.f32 "
                        "{%0,%1,%2,%3}, {%4,%5,%6,%7}, {%8,%9}, {%0,%1,%2,%3};"
                        : "+f"(acc[mt][nt][0]), "+f"(acc[mt][nt][1]),
                          "+f"(acc[mt][nt][2]), "+f"(acc[mt][nt][3])
                        : "r"(af[mt][0]), "r"(af[mt][1]),
                          "r"(af[mt][2]), "r"(af[mt][3]),
                          "r"(bf[nt][0]), "r"(bf[nt][1]));
                }
        }
        __syncthreads();
    }

    // ---- epilogue ----
#pragma unroll
    for (int mt = 0; mt < 4; mt++) {
#pragma unroll
        for (int nt = 0; nt < 4; nt++) {
            const int row = m0 + wm + mt * 16 + g;
            const int col = n0 + wn + nt * 8 + 2 * tig;
            *(float2*)&C[(size_t)row * N + col] =
                make_float2(acc[mt][nt][0], acc[mt][nt][1]);
            *(float2*)&C[(size_t)(row + 8) * N + col] =
                make_float2(acc[mt][nt][2], acc[mt][nt][3]);
        }
    }
}

// =================================================================
// RMSNorm + RoPE + layout rearrangement.
// Grid: (32 head-slots, 4096 tokens), 128 threads (one per dim).
// =================================================================
__global__ __launch_bounds__(128) void norm_rope(
    const float* __restrict__ qkv, const float* __restrict__ freqs,
    const float* __restrict__ qw, const float* __restrict__ kw,
    float* __restrict__ q, float* __restrict__ k, float* __restrict__ v)
{
    const int slot = blockIdx.x;   // 0..31
    const int bs   = blockIdx.y;   // 0..4095
    const int d    = threadIdx.x;  // 0..127
    const int b = bs >> 11;
    const int s = bs & 2047;

    const float val = qkv[(size_t)bs * QKV_O + slot * HDIM + d];

    if (slot < NH + NKVH) {
        const float w = (slot < NH) ? qw[d] : kw[d];
        float v2 = val * val;
#pragma unroll
        for (int o = 16; o > 0; o >>= 1)
            v2 += __shfl_xor_sync(0xffffffffu, v2, o);
        __shared__ float ws[4];
        if ((d & 31) == 0) ws[d >> 5] = v2;
        __syncthreads();
        const float ss = ws[0] + ws[1] + ws[2] + ws[3];
        const float r  = rsqrtf(ss * (1.0f / HDIM) + 1.1920928955078125e-07f);
        const float y  = val * r * w;
        const float part = __shfl_xor_sync(0xffffffffu, y, 1);
        const float* f = freqs + ((size_t)s * 64 + (d >> 1)) * 4;
        // even: cos*x0 - sin*x1 ; odd: sin*x0 + cos*x1 (coeffs taken from freqs)
        const float out = ((d & 1) == 0) ? (f[0] * y + f[1] * part)
                                         : (f[2] * part + f[3] * y);
        if (slot < NH)
            q[(((size_t)b * NH + slot) * SEQ + s) * HDIM + d] = out;
        else
            k[(((size_t)b * NKVH + (slot - NH)) * SEQ + s) * HDIM + d] = out;
    } else {
        v[(((size_t)b * NKVH + (slot - NH - NKVH)) * SEQ + s) * HDIM + d] = val;
    }
}

// =================================================================
// Flash attention fp32, non-causal, full softmax over K.
// 64-query x 64-key tiles, 256 threads, online softmax.
// =================================================================
#define FBQ 64
#define FBK 64
#define FKP 132   // padded row length for Qs/Ks/Vs (132 % 32 == 4)
#define FSP 68    // padded row length for score tile
#define FLASH_SMEM ((3 * FBQ * FKP + FBQ * FSP + 3 * FBQ) * 4)

__global__ __launch_bounds__(256) void flash_attn(
    const float* __restrict__ Qg, const float* __restrict__ Kg,
    const float* __restrict__ Vg, float* __restrict__ Og)
{
    extern __shared__ float sm[];
    float* Qs   = sm;                     // 64*132
    float* Ks   = Qs + FBQ * FKP;
    float* Vs   = Ks + FBK * FKP;
    float* Ss   = Vs + FBK * FKP;         // 64*68
    float* mrow = Ss + FBQ * FSP;
    float* lrow = mrow + FBQ;
    float* rsc  = lrow + FBQ;

    const int t  = threadIdx.x;
    const int b  = blockIdx.z;
    const int h  = blockIdx.y;
    const int q0 = blockIdx.x * FBQ;
    const int kvh = h >> 1;               // NREP = 2

    const float* Q = Qg + ((size_t)(b * NH + h) * SEQ + q0) * HDIM;
    const float* K = Kg + (size_t)(b * NKVH + kvh) * SEQ * HDIM;
    const float* V = Vg + (size_t)(b * NKVH + kvh) * SEQ * HDIM;

    const float scale = 0.08838834764831845f;   // 1/sqrt(128)

    // load Q tile (pre-scaled)
#pragma unroll
    for (int i = 0; i < 8; i++) {
        int e = (t + i * 256) * 4;
        int r = e >> 7, c = e & 127;
        float4 v4 = *(const float4*)(Q + e);
        float* dst = &Qs[r * FKP + c];
        dst[0] = v4.x * scale; dst[1] = v4.y * scale;
        dst[2] = v4.z * scale; dst[3] = v4.w * scale;
    }
    if (t < FBQ) { mrow[t] = -1e30f; lrow[t] = 0.f; }

    const int ty = t >> 4, tx = t & 15;
    const int rb = ty * 4;
    const int cb8 = tx * 8;

    float acc[4][8];
#pragma unroll
    for (int i = 0; i < 4; i++)
#pragma unroll
        for (int j = 0; j < 8; j++) acc[i][j] = 0.f;

    for (int kt = 0; kt < SEQ; kt += FBK) {
        __syncthreads();   // protect Ss/Vs readers of prev iter + Q stores (iter 0)
        // load K/V tiles
#pragma unroll
        for (int i = 0; i < 8; i++) {
            int e = (t + i * 256) * 4;
            int r = e >> 7, c = e & 127;
            float4 kv4 = *(const float4*)(K + (size_t)kt * HDIM + e);
            float4 vv4 = *(const float4*)(V + (size_t)kt * HDIM + e);
            float* dk = &Ks[r * FKP + c];
            dk[0] = kv4.x; dk[1] = kv4.y; dk[2] = kv4.z; dk[3] = kv4.w;
            *(float4*)&Vs[r * FKP + c] = vv4;
        }
        __syncthreads();

        // S = Q K^T  (thread cols: tx + 16*j for conflict control)
        float sreg[4][4];
#pragma unroll
        for (int i = 0; i < 4; i++)
#pragma unroll
            for (int j = 0; j < 4; j++) sreg[i][j] = 0.f;
#pragma unroll 4
        for (int kk = 0; kk < HDIM; kk++) {
            float qv[4], kvv[4];
#pragma unroll
            for (int i = 0; i < 4; i++) qv[i] = Qs[(rb + i) * FKP + kk];
#pragma unroll
            for (int j = 0; j < 4; j++) kvv[j] = Ks[(tx + 16 * j) * FKP + kk];
#pragma unroll
            for (int i = 0; i < 4; i++)
#pragma unroll
                for (int j = 0; j < 4; j++)
                    sreg[i][j] += qv[i] * kvv[j];
        }
#pragma unroll
        for (int i = 0; i < 4; i++)
#pragma unroll
            for (int j = 0; j < 4; j++)
                Ss[(rb + i) * FSP + tx + 16 * j] = sreg[i][j];
        __syncthreads();

        // online softmax: one thread per query row
        if (t < FBQ) {
            float* row = &Ss[t * FSP];
            const float mo = mrow[t];
            float mx = mo;
#pragma unroll 8
            for (int j = 0; j < FBK; j++) mx = fmaxf(mx, row[j]);
            const float sc = __expf(mo - mx);
            float sum = 0.f;
#pragma unroll 8
            for (int j = 0; j < FBK; j++) {
                float p = __expf(row[j] - mx);
                row[j] = p;
                sum += p;
            }
            lrow[t] = lrow[t] * sc + sum;
            mrow[t] = mx;
            rsc[t]  = sc;
        }
        __syncthreads();

        // rescale + O += P V
#pragma unroll
        for (int i = 0; i < 4; i++) {
            const float scv = rsc[rb + i];
#pragma unroll
            for (int j = 0; j < 8; j++) acc[i][j] *= scv;
        }
#pragma unroll 4
        for (int kk = 0; kk < FBK; kk++) {
            float pv[8];
            *(float4*)(pv)     = *(const float4*)&Vs[kk * FKP + cb8];
            *(float4*)(pv + 4) = *(const float4*)&Vs[kk * FKP + cb8 + 4];
#pragma unroll
            for (int i = 0; i < 4; i++) {
                const float p = Ss[(rb + i) * FSP + kk];
#pragma unroll
                for (int j = 0; j < 8; j++)
                    acc[i][j] += p * pv[j];
            }
        }
    }

    // epilogue: O /= l, write to [B,S,H*HD]
#pragma unroll
    for (int i = 0; i < 4; i++) {
        const float inv = 1.f / lrow[rb + i];
        float* o = Og + (size_t)(b * SEQ + q0 + rb + i) * (NH * HDIM) + h * HDIM + cb8;
        *(float4*)(o)     = make_float4(acc[i][0] * inv, acc[i][1] * inv,
                                        acc[i][2] * inv, acc[i][3] * inv);
        *(float4*)(o + 4) = make_float4(acc[i][4] * inv, acc[i][5] * inv,
                                        acc[i][6] * inv, acc[i][7] * inv);
    }
}

// =================================================================
extern "C" void kernel_launch(void* const* d_in, const int* in_sizes, int n_in,
                              void* d_out, int out_size)
{
    const float* x      = (const float*)d_in[0];
    // d_in[1] = x_mask (unused by forward)
    const float* freqs  = (const float*)d_in[2];
    const float* w_qkv  = (const float*)d_in[3];
    const float* w_out  = (const float*)d_in[4];
    const float* qw     = (const float*)d_in[5];
    const float* kw     = (const float*)d_in[6];
    float* out = (float*)d_out;

    float *qkvb, *qb, *kb, *vb, *aob;
    cudaGetSymbolAddress((void**)&qkvb, g_qkv);
    cudaGetSymbolAddress((void**)&qb, g_q);
    cudaGetSymbolAddress((void**)&kb, g_k);
    cudaGetSymbolAddress((void**)&vb, g_v);
    cudaGetSymbolAddress((void**)&aob, g_ao);

    cudaFuncSetAttribute(flash_attn, cudaFuncAttributeMaxDynamicSharedMemorySize,
                         FLASH_SMEM);

    // 1) QKV projection: [4096,2048] x [4096,2048]^T(NT) -> [4096,4096]
    gemm_nt_tf32<<<dim3(QKV_O / 128, NTOK / 128), 256>>>(x, w_qkv, qkvb,
                                                         NTOK, QKV_O, DIM);
    // 2) RMSNorm + RoPE + relayout
    norm_rope<<<dim3(NH + 2 * NKVH, NTOK), 128>>>(qkvb, freqs, qw, kw, qb, kb, vb);
    // 3) attention
    flash_attn<<<dim3(SEQ / FBQ, NH, BATCH), 256, FLASH_SMEM>>>(qb, kb, vb, aob);
    // 4) output projection -> d_out
    gemm_nt_tf32<<<dim3(DIM / 128, NTOK / 128), 256>>>(aob, w_out, out,
                                                       NTOK, DIM, NH * HDIM);
}

// round 9
// speedup vs baseline: 1.5770x; 1.5770x over previous
#include <cuda_runtime.h>
#include <math.h>
#include <stdint.h>

#define BATCH 2
#define SEQ   2048
#define DIM   2048
#define NH    16
#define NKVH  8
#define HDIM  128
#define NREP  2
#define QKV_O ((NH + 2 * NKVH) * HDIM)   // 4096
#define NTOK  (BATCH * SEQ)              // 4096

// ---------------- scratch (no allocations allowed) ----------------
__device__ float g_qkv[(size_t)NTOK * QKV_O];          // 64 MB
__device__ float g_q[(size_t)BATCH * NH * SEQ * HDIM]; // 32 MB
__device__ float g_k[(size_t)BATCH * NKVH * SEQ * HDIM];
__device__ float g_v[(size_t)BATCH * NKVH * SEQ * HDIM];
__device__ float g_ao[(size_t)NTOK * NH * HDIM];       // 32 MB

__device__ __forceinline__ uint32_t f2tf32(float x) {
    uint32_t u;
    asm("cvt.rna.tf32.f32 %0, %1;" : "=r"(u) : "f"(x));
    return u;
}

// =================================================================
// tf32 tensor-core NT GEMM: C[m,n] = sum_k A[m*K+k] * B[n*K+k]
// 128x128 block tile, BK=32, 256 threads (8 warps as 2x4),
// warp tile 64x32 = 4x4 mma.m16n8k8 tiles, fp32 accumulate.
// =================================================================
#define TBK 32
#define TST 36   // SMEM row stride (floats): conflict-free fragment LDS

__global__ __launch_bounds__(256) void gemm_nt_tf32(
    const float* __restrict__ A, const float* __restrict__ Bm,
    float* __restrict__ C, int M, int N, int K)
{
    __shared__ float As[128 * TST];
    __shared__ float Bs[128 * TST];

    const int t    = threadIdx.x;
    const int lane = t & 31;
    const int wid  = t >> 5;
    const int g    = lane >> 2;     // groupID 0..7
    const int tig  = lane & 3;      // thread-in-group 0..3
    const int wm   = (wid >> 2) * 64;   // warp M offset in tile
    const int wn   = (wid & 3) * 32;    // warp N offset in tile

    const int m0 = blockIdx.y * 128;
    const int n0 = blockIdx.x * 128;

    const int lrow = t >> 1;            // 0..127
    const int lkb  = (t & 1) * 16;      // 0 or 16

    const float* Ag = A  + (size_t)(m0 + lrow) * K + lkb;
    const float* Bg = Bm + (size_t)(n0 + lrow) * K + lkb;

    float acc[4][4][4];
#pragma unroll
    for (int i = 0; i < 4; i++)
#pragma unroll
        for (int j = 0; j < 4; j++)
#pragma unroll
            for (int c = 0; c < 4; c++) acc[i][j][c] = 0.f;

    for (int k0 = 0; k0 < K; k0 += TBK) {
        // ---- load 128x32 A and B tiles, round to tf32, store k-major ----
#pragma unroll
        for (int i = 0; i < 4; i++) {
            float4 a = *(const float4*)(Ag + k0 + i * 4);
            float4 b = *(const float4*)(Bg + k0 + i * 4);
            float4 at, bt;
            at.x = __uint_as_float(f2tf32(a.x)); at.y = __uint_as_float(f2tf32(a.y));
            at.z = __uint_as_float(f2tf32(a.z)); at.w = __uint_as_float(f2tf32(a.w));
            bt.x = __uint_as_float(f2tf32(b.x)); bt.y = __uint_as_float(f2tf32(b.y));
            bt.z = __uint_as_float(f2tf32(b.z)); bt.w = __uint_as_float(f2tf32(b.w));
            *(float4*)&As[lrow * TST + lkb + i * 4] = at;
            *(float4*)&Bs[lrow * TST + lkb + i * 4] = bt;
        }
        __syncthreads();

        // ---- 4 k-chunks of 8 ----
#pragma unroll
        for (int kc = 0; kc < 4; kc++) {
            uint32_t af[4][4];
            uint32_t bf[4][2];
#pragma unroll
            for (int mt = 0; mt < 4; mt++) {
                const float* p = &As[(wm + mt * 16 + g) * TST + kc * 8 + tig];
                af[mt][0] = __float_as_uint(p[0]);
                af[mt][1] = __float_as_uint(p[8 * TST]);
                af[mt][2] = __float_as_uint(p[4]);
                af[mt][3] = __float_as_uint(p[8 * TST + 4]);
            }
#pragma unroll
            for (int nt = 0; nt < 4; nt++) {
                const float* p = &Bs[(wn + nt * 8 + g) * TST + kc * 8 + tig];
                bf[nt][0] = __float_as_uint(p[0]);
                bf[nt][1] = __float_as_uint(p[4]);
            }
#pragma unroll
            for (int mt = 0; mt < 4; mt++)
#pragma unroll
                for (int nt = 0; nt < 4; nt++) {
                    asm volatile(
                        "mma.sync.aligned.m16n8k8.row.col.f32.tf32.tf32.f32 "
                        "{%0,%1,%2,%3}, {%4,%5,%6,%7}, {%8,%9}, {%0,%1,%2,%3};"
                        : "+f"(acc[mt][nt][0]), "+f"(acc[mt][nt][1]),
                          "+f"(acc[mt][nt][2]), "+f"(acc[mt][nt][3])
                        : "r"(af[mt][0]), "r"(af[mt][1]),
                          "r"(af[mt][2]), "r"(af[mt][3]),
                          "r"(bf[nt][0]), "r"(bf[nt][1]));
                }
        }
        __syncthreads();
    }

    // ---- epilogue ----
#pragma unroll
    for (int mt = 0; mt < 4; mt++) {
#pragma unroll
        for (int nt = 0; nt < 4; nt++) {
            const int row = m0 + wm + mt * 16 + g;
            const int col = n0 + wn + nt * 8 + 2 * tig;
            *(float2*)&C[(size_t)row * N + col] =
                make_float2(acc[mt][nt][0], acc[mt][nt][1]);
            *(float2*)&C[(size_t)(row + 8) * N + col] =
                make_float2(acc[mt][nt][2], acc[mt][nt][3]);
        }
    }
}

// =================================================================
// RMSNorm + RoPE + layout rearrangement.
// Grid: (32 head-slots, 4096 tokens), 128 threads (one per dim).
// =================================================================
__global__ __launch_bounds__(128) void norm_rope(
    const float* __restrict__ qkv, const float* __restrict__ freqs,
    const float* __restrict__ qw, const float* __restrict__ kw,
    float* __restrict__ q, float* __restrict__ k, float* __restrict__ v)
{
    const int slot = blockIdx.x;   // 0..31
    const int bs   = blockIdx.y;   // 0..4095
    const int d    = threadIdx.x;  // 0..127
    const int b = bs >> 11;
    const int s = bs & 2047;

    const float val = qkv[(size_t)bs * QKV_O + slot * HDIM + d];

    if (slot < NH + NKVH) {
        const float w = (slot < NH) ? qw[d] : kw[d];
        float v2 = val * val;
#pragma unroll
        for (int o = 16; o > 0; o >>= 1)
            v2 += __shfl_xor_sync(0xffffffffu, v2, o);
        __shared__ float ws[4];
        if ((d & 31) == 0) ws[d >> 5] = v2;
        __syncthreads();
        const float ss = ws[0] + ws[1] + ws[2] + ws[3];
        const float r  = rsqrtf(ss * (1.0f / HDIM) + 1.1920928955078125e-07f);
        const float y  = val * r * w;
        const float part = __shfl_xor_sync(0xffffffffu, y, 1);
        const float* f = freqs + ((size_t)s * 64 + (d >> 1)) * 4;
        // even: cos*x0 - sin*x1 ; odd: sin*x0 + cos*x1 (coeffs taken from freqs)
        const float out = ((d & 1) == 0) ? (f[0] * y + f[1] * part)
                                         : (f[2] * part + f[3] * y);
        if (slot < NH)
            q[(((size_t)b * NH + slot) * SEQ + s) * HDIM + d] = out;
        else
            k[(((size_t)b * NKVH + (slot - NH)) * SEQ + s) * HDIM + d] = out;
    } else {
        v[(((size_t)b * NKVH + (slot - NH - NKVH)) * SEQ + s) * HDIM + d] = val;
    }
}

// =================================================================
// Tensor-core flash attention (tf32 mma, fp32 softmax/accum).
// 64-query x 64-key tiles, 256 threads (8 warps), online softmax.
// SMEM: Qs/Ks [64][132] tf32, Vt [128][68] tf32 (transposed),
//       Ss [64][68] scores->P(tf32), m/l/rescale rows.
// =================================================================
#define QST 132
#define SST 68
#define VST 68
#define ATT_SMEM ((64*QST + 64*QST + 128*VST + 64*SST + 3*64) * 4)

__global__ __launch_bounds__(256) void flash_attn_tc(
    const float* __restrict__ Qg, const float* __restrict__ Kg,
    const float* __restrict__ Vg, float* __restrict__ Og)
{
    extern __shared__ float sm[];
    float* Qs   = sm;                   // 64*132
    float* Ks   = Qs + 64 * QST;        // 64*132
    float* Vt   = Ks + 64 * QST;        // 128*68 (transposed: [d][key])
    float* Ss   = Vt + 128 * VST;       // 64*68
    float* mrow = Ss + 64 * SST;
    float* lrow = mrow + 64;
    float* rsc  = lrow + 64;

    const int t    = threadIdx.x;
    const int lane = t & 31;
    const int wid  = t >> 5;
    const int g    = lane >> 2;
    const int tig  = lane & 3;

    const int b   = blockIdx.z;
    const int h   = blockIdx.y;
    const int q0  = blockIdx.x * 64;
    const int kvh = h >> 1;             // NREP = 2

    const float* Q = Qg + ((size_t)(b * NH + h) * SEQ + q0) * HDIM;
    const float* K = Kg + (size_t)(b * NKVH + kvh) * SEQ * HDIM;
    const float* V = Vg + (size_t)(b * NKVH + kvh) * SEQ * HDIM;

    const float scale = 0.08838834764831845f;   // 1/sqrt(128)

    // ---- load Q tile once: scale + tf32, [q][d] stride 132 ----
#pragma unroll
    for (int i = 0; i < 8; i++) {
        int e = (t + i * 256) * 4;
        int r = e >> 7, c = e & 127;
        float4 v4 = *(const float4*)(Q + e);
        float* dst = &Qs[r * QST + c];
        dst[0] = __uint_as_float(f2tf32(v4.x * scale));
        dst[1] = __uint_as_float(f2tf32(v4.y * scale));
        dst[2] = __uint_as_float(f2tf32(v4.z * scale));
        dst[3] = __uint_as_float(f2tf32(v4.w * scale));
    }
    if (t < 64) { mrow[t] = -1e30f; lrow[t] = 0.f; }

    // warp tiling: S-phase 16x32 (4x2 warps), PV-phase 16x64
    const int wm  = (wid >> 1) * 16;
    const int wn  = (wid & 1) * 32;
    const int wn2 = (wid & 1) * 64;

    // V transpose-load assignment: 32 keys per warp (bank = lane on STS)
    const int vkey = lane + (wid & 1) * 32;
    const int vdb  = (wid >> 1) * 32;

    float oacc[8][4];
#pragma unroll
    for (int nt = 0; nt < 8; nt++)
#pragma unroll
        for (int c = 0; c < 4; c++) oacc[nt][c] = 0.f;

    for (int kt = 0; kt < SEQ; kt += 64) {
        __syncthreads();   // prev iter's Ss/Vt/Ks consumers done (also Q @ iter0)

        // ---- K tile: coalesced, tf32, [key][d] stride 132 ----
#pragma unroll
        for (int i = 0; i < 8; i++) {
            int e = (t + i * 256) * 4;
            int r = e >> 7, c = e & 127;
            float4 kv = *(const float4*)(K + (size_t)kt * HDIM + e);
            float* dk = &Ks[r * QST + c];
            dk[0] = __uint_as_float(f2tf32(kv.x));
            dk[1] = __uint_as_float(f2tf32(kv.y));
            dk[2] = __uint_as_float(f2tf32(kv.z));
            dk[3] = __uint_as_float(f2tf32(kv.w));
        }
        // ---- V tile: transposed into Vt[d][key], conflict-free STS ----
        {
            const float* vrow = V + (size_t)(kt + vkey) * HDIM;
#pragma unroll
            for (int i = 0; i < 8; i++) {
                int d0 = vdb + i * 4;
                float4 vv = *(const float4*)(vrow + d0);
                Vt[(d0 + 0) * VST + vkey] = __uint_as_float(f2tf32(vv.x));
                Vt[(d0 + 1) * VST + vkey] = __uint_as_float(f2tf32(vv.y));
                Vt[(d0 + 2) * VST + vkey] = __uint_as_float(f2tf32(vv.z));
                Vt[(d0 + 3) * VST + vkey] = __uint_as_float(f2tf32(vv.w));
            }
        }
        __syncthreads();

        // ---- S = Q K^T via tensor cores ----
        float sacc[4][4];
#pragma unroll
        for (int nt = 0; nt < 4; nt++)
#pragma unroll
            for (int c = 0; c < 4; c++) sacc[nt][c] = 0.f;
#pragma unroll
        for (int kc = 0; kc < 16; kc++) {
            uint32_t af[4];
            const float* pa = &Qs[(wm + g) * QST + kc * 8 + tig];
            af[0] = __float_as_uint(pa[0]);
            af[1] = __float_as_uint(pa[8 * QST]);
            af[2] = __float_as_uint(pa[4]);
            af[3] = __float_as_uint(pa[8 * QST + 4]);
            uint32_t bf[4][2];
#pragma unroll
            for (int nt = 0; nt < 4; nt++) {
                const float* pb = &Ks[(wn + nt * 8 + g) * QST + kc * 8 + tig];
                bf[nt][0] = __float_as_uint(pb[0]);
                bf[nt][1] = __float_as_uint(pb[4]);
            }
#pragma unroll
            for (int nt = 0; nt < 4; nt++) {
                asm volatile(
                    "mma.sync.aligned.m16n8k8.row.col.f32.tf32.tf32.f32 "
                    "{%0,%1,%2,%3}, {%4,%5,%6,%7}, {%8,%9}, {%0,%1,%2,%3};"
                    : "+f"(sacc[nt][0]), "+f"(sacc[nt][1]),
                      "+f"(sacc[nt][2]), "+f"(sacc[nt][3])
                    : "r"(af[0]), "r"(af[1]), "r"(af[2]), "r"(af[3]),
                      "r"(bf[nt][0]), "r"(bf[nt][1]));
            }
        }
        // store S fragments to Ss
#pragma unroll
        for (int nt = 0; nt < 4; nt++) {
            float* s0 = &Ss[(wm + g) * SST + wn + nt * 8 + 2 * tig];
            *(float2*)s0            = make_float2(sacc[nt][0], sacc[nt][1]);
            *(float2*)(s0 + 8*SST)  = make_float2(sacc[nt][2], sacc[nt][3]);
        }
        __syncthreads();

        // ---- online softmax: 4 threads per query row ----
        {
            const int row = t >> 2, sub = t & 3;
            float* rp = &Ss[row * SST + sub * 16];
            float mx = rp[0];
#pragma unroll
            for (int j = 1; j < 16; j++) mx = fmaxf(mx, rp[j]);
            mx = fmaxf(mx, __shfl_xor_sync(0xffffffffu, mx, 1));
            mx = fmaxf(mx, __shfl_xor_sync(0xffffffffu, mx, 2));
            const float mo = mrow[row];
            const float mn = fmaxf(mo, mx);
            float sum = 0.f;
#pragma unroll
            for (int j = 0; j < 16; j++) {
                float p = __expf(rp[j] - mn);
                rp[j] = __uint_as_float(f2tf32(p));
                sum += p;
            }
            sum += __shfl_xor_sync(0xffffffffu, sum, 1);
            sum += __shfl_xor_sync(0xffffffffu, sum, 2);
            if (sub == 0) {
                const float sc = __expf(mo - mn);
                rsc[row]  = sc;
                lrow[row] = lrow[row] * sc + sum;
                mrow[row] = mn;
            }
        }
        __syncthreads();

        // ---- rescale O accumulators, then O += P V ----
        {
            const float sc0 = rsc[wm + g];
            const float sc1 = rsc[wm + g + 8];
#pragma unroll
            for (int nt = 0; nt < 8; nt++) {
                oacc[nt][0] *= sc0; oacc[nt][1] *= sc0;
                oacc[nt][2] *= sc1; oacc[nt][3] *= sc1;
            }
        }
#pragma unroll
        for (int kc = 0; kc < 8; kc++) {
            uint32_t af[4];
            const float* pa = &Ss[(wm + g) * SST + kc * 8 + tig];
            af[0] = __float_as_uint(pa[0]);
            af[1] = __float_as_uint(pa[8 * SST]);
            af[2] = __float_as_uint(pa[4]);
            af[3] = __float_as_uint(pa[8 * SST + 4]);
#pragma unroll
            for (int nt = 0; nt < 8; nt++) {
                const float* pb = &Vt[(wn2 + nt * 8 + g) * VST + kc * 8 + tig];
                uint32_t b0 = __float_as_uint(pb[0]);
                uint32_t b1 = __float_as_uint(pb[4]);
                asm volatile(
                    "mma.sync.aligned.m16n8k8.row.col.f32.tf32.tf32.f32 "
                    "{%0,%1,%2,%3}, {%4,%5,%6,%7}, {%8,%9}, {%0,%1,%2,%3};"
                    : "+f"(oacc[nt][0]), "+f"(oacc[nt][1]),
                      "+f"(oacc[nt][2]), "+f"(oacc[nt][3])
                    : "r"(af[0]), "r"(af[1]), "r"(af[2]), "r"(af[3]),
                      "r"(b0), "r"(b1));
            }
        }
    }

    // ---- epilogue: O /= l, write [B,S,H*HD] ----
    const float inv0 = 1.f / lrow[wm + g];
    const float inv1 = 1.f / lrow[wm + g + 8];
#pragma unroll
    for (int nt = 0; nt < 8; nt++) {
        const int col = h * HDIM + wn2 + nt * 8 + 2 * tig;
        float* o0 = Og + (size_t)(b * SEQ + q0 + wm + g) * (NH * HDIM) + col;
        float* o1 = Og + (size_t)(b * SEQ + q0 + wm + g + 8) * (NH * HDIM) + col;
        *(float2*)o0 = make_float2(oacc[nt][0] * inv0, oacc[nt][1] * inv0);
        *(float2*)o1 = make_float2(oacc[nt][2] * inv1, oacc[nt][3] * inv1);
    }
}

// =================================================================
extern "C" void kernel_launch(void* const* d_in, const int* in_sizes, int n_in,
                              void* d_out, int out_size)
{
    const float* x      = (const float*)d_in[0];
    // d_in[1] = x_mask (unused by forward)
    const float* freqs  = (const float*)d_in[2];
    const float* w_qkv  = (const float*)d_in[3];
    const float* w_out  = (const float*)d_in[4];
    const float* qw     = (const float*)d_in[5];
    const float* kw     = (const float*)d_in[6];
    float* out = (float*)d_out;

    float *qkvb, *qb, *kb, *vb, *aob;
    cudaGetSymbolAddress((void**)&qkvb, g_qkv);
    cudaGetSymbolAddress((void**)&qb, g_q);
    cudaGetSymbolAddress((void**)&kb, g_k);
    cudaGetSymbolAddress((void**)&vb, g_v);
    cudaGetSymbolAddress((void**)&aob, g_ao);

    cudaFuncSetAttribute(flash_attn_tc, cudaFuncAttributeMaxDynamicSharedMemorySize,
                         ATT_SMEM);

    // 1) QKV projection: [4096,2048] x [4096,2048]^T(NT) -> [4096,4096]
    gemm_nt_tf32<<<dim3(QKV_O / 128, NTOK / 128), 256>>>(x, w_qkv, qkvb,
                                                         NTOK, QKV_O, DIM);
    // 2) RMSNorm + RoPE + relayout
    norm_rope<<<dim3(NH + 2 * NKVH, NTOK), 128>>>(qkvb, freqs, qw, kw, qb, kb, vb);
    // 3) attention (tensor cores)
    flash_attn_tc<<<dim3(SEQ / 64, NH, BATCH), 256, ATT_SMEM>>>(qb, kb, vb, aob);
    // 4) output projection -> d_out
    gemm_nt_tf32<<<dim3(DIM / 128, NTOK / 128), 256>>>(aob, w_out, out,
                                                       NTOK, DIM, NH * HDIM);
}